// round 13
// baseline (speedup 1.0000x reference)
#include <cuda_runtime.h>
#include <cstdint>
#include <math_constants.h>

// Problem constants
#define N_VEC 65536
#define DIM   256
#define KCB   1024
#define NC    4

// GEMM tiling
#define BM 128
#define BN 128
#define BK 16
#define PITCH 132   // padded smem pitch (floats) to break bank conflicts

// Compact-loss tiling
#define CTI 16
#define CNT (KCB / CTI)                   // 64 tiles per axis
#define CPAIRS (CNT * (CNT + 1) / 2)      // 2080 triangular tile pairs
#define CPITCH 260                        // padded pitch (floats), 16B-aligned

// ---------------- device scratch (no allocation allowed) ----------------
__device__ float  g_resid[(size_t)N_VEC * DIM];   // 64 MB residual buffer
__device__ float  g_wsq[NC * KCB];                // ||w||^2 per codeword
__device__ int    g_counts[NC * KCB];             // bincount per level
__device__ double g_quant;                        // sum (q - r)^2
__device__ double g_compact;                      // sum of pairwise distances

// ---------------- fused init + ||w||^2 ----------------
// Thread i (0..NC*KCB-1): clears counters/scalars AND computes ||w_i||^2 with
// a strictly sequential ascending-d sum (mimic reference rounding).
// (The quantized output region is fully overwritten by vq level 0, so no
//  64 MB zero-fill is needed.)
__global__ void init_wsq_kernel(const float* __restrict__ cb) {
    int i = blockIdx.x * blockDim.x + threadIdx.x;   // 0..NC*KCB-1
    if (i >= NC * KCB) return;
    g_counts[i] = 0;
    if (i == 0) { g_quant = 0.0; g_compact = 0.0; }
    const float* w = cb + (size_t)i * DIM;
    float acc = 0.0f;
    for (int d = 0; d < DIM; ++d)
        acc = __fadd_rn(acc, __fmul_rn(w[d], w[d]));
    g_wsq[i] = acc;
}

// ---------------- fused per-level VQ: GEMM + argmin + update ----------------
__global__ __launch_bounds__(256, 2) void vq_level_kernel(
    const float* __restrict__ x,
    const float* __restrict__ cb,
    float* __restrict__ out_q,      // quantized [N][D] (accumulated)
    float* __restrict__ out_idx,    // idx for this level, as float [N]
    int level)
{
    const float* W   = cb + (size_t)level * KCB * DIM;
    const float* wsq = g_wsq + level * KCB;
    int*  counts     = g_counts + level * KCB;
    const float* resid_src = (level == 0) ? x : g_resid;
    float* resid_dst = g_resid;

    // Shared pool: As/Bs (mainloop) alias redv/redi (post-loop reduction).
    // Lifetimes are disjoint; a __syncthreads() separates them.
    // Size: 2 bufs * 2 arrays * BK*PITCH floats = 8448 floats = 33792 B.
    __shared__ float pool[2 * 2 * BK * PITCH];
    __shared__ float rowHalf[2 * BM];   // partial r*r sums (2 halves per row)
    __shared__ float rowA[BM];
    __shared__ int   bidx[BM];

    float (*As)[BK][PITCH] = reinterpret_cast<float (*)[BK][PITCH]>(pool);
    float (*Bs)[BK][PITCH] = reinterpret_cast<float (*)[BK][PITCH]>(pool + 2 * BK * PITCH);
    float (*redv)[17]      = reinterpret_cast<float (*)[17]>(pool);              // 2176 floats
    int   (*redi)[17]      = reinterpret_cast<int (*)[17]>(pool + 2176);         // 2176 ints

    const int tid = threadIdx.x;
    const int tx = tid & 15;        // col group
    const int ty = tid >> 4;        // row group
    const int row0 = blockIdx.x * BM;

    // Per-thread fixed cooperative-load coordinates (2 float4 each for A and B)
    const int rr0 = tid >> 2,         dd0 = (tid & 3) * 4;          // rows 0..63
    const int rr1 = (tid + 256) >> 2, dd1 = ((tid + 256) & 3) * 4;  // rows 64..127

    // Per-row A = sum fl(r*r): 2 threads/row, each a strict sequential half,
    // combined with one add. Differs from a fully-serial sum by <=1-2 ulp,
    // UNIFORMLY per row -> fl(A+B_k) shifts identically for all k (same
    // binade, grid-multiple delta) -> argmin provably unaffected.
    {
        const int r  = tid >> 1;               // 0..127
        const int h  = tid & 1;                // half
        const float* p = resid_src + (size_t)(row0 + r) * DIM + h * (DIM / 2);
        float a = 0.0f;
        for (int d = 0; d < DIM / 2; ++d)
            a = __fadd_rn(a, __fmul_rn(p[d], p[d]));
        rowHalf[r * 2 + h] = a;
    }

    float aA[8];
    float minv[8];
    int   mini[8];

    // Prefetch slice (chunk=0, s=0) into registers
    float4 pa0 = *(const float4*)(resid_src + (size_t)(row0 + rr0) * DIM + dd0);
    float4 pa1 = *(const float4*)(resid_src + (size_t)(row0 + rr1) * DIM + dd1);
    float4 pb0 = *(const float4*)(W + (size_t)rr0 * DIM + dd0);
    float4 pb1 = *(const float4*)(W + (size_t)rr1 * DIM + dd1);
    __syncthreads();   // rowHalf ready

    if (tid < BM)
        rowA[tid] = __fadd_rn(rowHalf[tid * 2], rowHalf[tid * 2 + 1]);
    __syncthreads();   // rowA ready

    #pragma unroll
    for (int i = 0; i < 8; ++i) {
        aA[i]   = rowA[ty * 8 + i];
        minv[i] = CUDART_INF_F;
        mini[i] = 0;
    }

    int slice = 0;   // global slice counter -> buffer parity
    for (int chunk = 0; chunk < KCB / BN; ++chunk) {
        float acc[8][8];
        #pragma unroll
        for (int i = 0; i < 8; ++i)
            #pragma unroll
            for (int j = 0; j < 8; ++j) acc[i][j] = 0.0f;

        for (int s = 0; s < DIM / BK; ++s, ++slice) {
            const int buf = slice & 1;

            // Store the prefetched slice into smem buffer `buf`
            // (consumes pa*/pb* register values in program order)
            As[buf][dd0 + 0][rr0] = pa0.x; As[buf][dd0 + 1][rr0] = pa0.y;
            As[buf][dd0 + 2][rr0] = pa0.z; As[buf][dd0 + 3][rr0] = pa0.w;
            As[buf][dd1 + 0][rr1] = pa1.x; As[buf][dd1 + 1][rr1] = pa1.y;
            As[buf][dd1 + 2][rr1] = pa1.z; As[buf][dd1 + 3][rr1] = pa1.w;
            Bs[buf][dd0 + 0][rr0] = pb0.x; Bs[buf][dd0 + 1][rr0] = pb0.y;
            Bs[buf][dd0 + 2][rr0] = pb0.z; Bs[buf][dd0 + 3][rr0] = pb0.w;
            Bs[buf][dd1 + 0][rr1] = pb1.x; Bs[buf][dd1 + 1][rr1] = pb1.y;
            Bs[buf][dd1 + 2][rr1] = pb1.z; Bs[buf][dd1 + 3][rr1] = pb1.w;

            // Issue the NEXT slice's global loads BEFORE the barrier so their
            // latency overlaps the barrier wait AND the FMA block below.
            // Registers are dead after the smem stores above (in-order WAR safe).
            const bool last = (chunk == KCB / BN - 1) && (s == DIM / BK - 1);
            if (!last) {
                int nchunk = chunk, ns = s + 1;
                if (ns == DIM / BK) { ns = 0; ++nchunk; }
                const int nd0 = ns * BK;
                pa0 = *(const float4*)(resid_src + (size_t)(row0 + rr0) * DIM + nd0 + dd0);
                pa1 = *(const float4*)(resid_src + (size_t)(row0 + rr1) * DIM + nd0 + dd1);
                pb0 = *(const float4*)(W + (size_t)(nchunk * BN + rr0) * DIM + nd0 + dd0);
                pb1 = *(const float4*)(W + (size_t)(nchunk * BN + rr1) * DIM + nd0 + dd1);
            }
            __syncthreads();   // single barrier per slice (double-buffered)

            // 8x8 register micro-tile over the current buffer
            #pragma unroll
            for (int kk = 0; kk < BK; ++kk) {
                float4 a0 = *(const float4*)&As[buf][kk][ty * 8];
                float4 a1 = *(const float4*)&As[buf][kk][ty * 8 + 4];
                float4 b0 = *(const float4*)&Bs[buf][kk][tx * 8];
                float4 b1 = *(const float4*)&Bs[buf][kk][tx * 8 + 4];
                float av[8] = {a0.x, a0.y, a0.z, a0.w, a1.x, a1.y, a1.z, a1.w};
                float bv[8] = {b0.x, b0.y, b0.z, b0.w, b1.x, b1.y, b1.z, b1.w};
                #pragma unroll
                for (int i = 0; i < 8; ++i)
                    #pragma unroll
                    for (int j = 0; j < 8; ++j)
                        acc[i][j] = fmaf(av[i], bv[j], acc[i][j]);
            }
            // No trailing barrier: the next iteration targets the OTHER buffer,
            // and its barrier orders reuse of this one.
        }

        // dist_k = fl( fl(A + B_k) - fl(2*C_k) ), exactly as ref: (A+B) - 2*C
        #pragma unroll
        for (int j = 0; j < 8; ++j) {
            const int col = chunk * BN + tx * 8 + j;     // ascending over chunk,j
            const float bw = __ldg(&wsq[col]);
            #pragma unroll
            for (int i = 0; i < 8; ++i) {
                float t1 = __fadd_rn(aA[i], bw);
                float t2 = __fmul_rn(2.0f, acc[i][j]);
                float d  = __fsub_rn(t1, t2);
                if (d < minv[i]) { minv[i] = d; mini[i] = col; }  // first-min tie-break
            }
        }
    }

    // Barrier BEFORE reusing the As/Bs pool as reduction scratch (aliasing).
    __syncthreads();

    // Cross-thread argmin reduce (lexicographic on (value, index))
    #pragma unroll
    for (int i = 0; i < 8; ++i) {
        redv[ty * 8 + i][tx] = minv[i];
        redi[ty * 8 + i][tx] = mini[i];
    }
    __syncthreads();
    if (tid < BM) {
        float bv = redv[tid][0]; int bi = redi[tid][0];
        #pragma unroll
        for (int t = 1; t < 16; ++t) {
            float v = redv[tid][t]; int ii = redi[tid][t];
            if (v < bv || (v == bv && ii < bi)) { bv = v; bi = ii; }
        }
        bidx[tid] = bi;
        out_idx[row0 + tid] = (float)bi;
        atomicAdd(&counts[bi], 1);
    }
    __syncthreads();

    // Vector epilogue: warp-per-row, coalesced float4.
    // Level 0: quantized = q (full overwrite; fl(0+q) == q bitwise, so no
    //          zero-init and no read of out_q needed).
    // Level >0: quantized += q.
    // Then residual = x - quantized ; accumulate (q - r_old)^2.
    const int warp = tid >> 5, lane = tid & 31;
    const bool first_level = (level == 0);
    const bool write_resid = (level != NC - 1);   // last level's residual is dead
    double dacc = 0.0;
    for (int rr = warp; rr < BM; rr += 8) {
        const int R = row0 + rr;
        const int idx = bidx[rr];
        const float4* q4  = (const float4*)(W + (size_t)idx * DIM);
        const float4* x4  = (const float4*)(x + (size_t)R * DIM);
        const float4* rs4 = (const float4*)(resid_src + (size_t)R * DIM);
        float4* qz4 = (float4*)(out_q + (size_t)R * DIM);
        float4* rd4 = (float4*)(resid_dst + (size_t)R * DIM);
        #pragma unroll
        for (int t = 0; t < 2; ++t) {
            const int p = lane + t * 32;
            float4 q  = q4[p];
            float4 xx = x4[p];
            float4 rs = rs4[p];
            float4 nq, nr;
            if (first_level) {
                nq = q;   // == fl(0 + q) bitwise
            } else {
                float4 qz = qz4[p];
                nq.x = __fadd_rn(qz.x, q.x); nq.y = __fadd_rn(qz.y, q.y);
                nq.z = __fadd_rn(qz.z, q.z); nq.w = __fadd_rn(qz.w, q.w);
            }
            nr.x = __fsub_rn(xx.x, nq.x); nr.y = __fsub_rn(xx.y, nq.y);
            nr.z = __fsub_rn(xx.z, nq.z); nr.w = __fsub_rn(xx.w, nq.w);
            qz4[p] = nq;
            if (write_resid) rd4[p] = nr;
            float d0 = __fsub_rn(q.x, rs.x);
            float d1 = __fsub_rn(q.y, rs.y);
            float d2 = __fsub_rn(q.z, rs.z);
            float d3 = __fsub_rn(q.w, rs.w);
            dacc += (double)d0 * d0 + (double)d1 * d1
                  + (double)d2 * d2 + (double)d3 * d3;
        }
    }
    #pragma unroll
    for (int off = 16; off; off >>= 1)
        dacc += __shfl_down_sync(0xffffffffu, dacc, off);
    if (lane == 0) atomicAdd(&g_quant, dacc);
}

// ---------------- compact loss: tiled pdist over codewords ----------------
// Grid: NC * CPAIRS blocks. Block handles a (ti, tj) tile pair (ti <= tj) of
// 16x16 codewords; both tiles cached in smem, 1 pair per thread, float4 dot.
__global__ __launch_bounds__(256) void compact_kernel(const float* __restrict__ cb) {
    const int c = blockIdx.x / CPAIRS;
    int p = blockIdx.x % CPAIRS;
    int ti = 0;
    while (p >= CNT - ti) { p -= CNT - ti; ++ti; }
    const int tj = ti + p;
    const float* Wl = cb + (size_t)c * KCB * DIM;

    __shared__ float Wi[CTI][CPITCH];
    __shared__ float Wj[CTI][CPITCH];
    __shared__ double wsum[8];

    const int tid = threadIdx.x;
    // Cooperative tile loads: 16 rows x 64 float4 per tile
    {
        const int r = tid >> 4;           // 0..15
        const int q = tid & 15;           // 0..15 -> 4 float4 each
        const float* srcI = Wl + (size_t)(ti * CTI + r) * DIM;
        const float* srcJ = Wl + (size_t)(tj * CTI + r) * DIM;
        #pragma unroll
        for (int u = 0; u < 4; ++u) {
            const int d4 = q * 4 + u;     // 0..63
            float4 vi = *(const float4*)(srcI + d4 * 4);
            *(float4*)&Wi[r][d4 * 4] = vi;
            float4 vj = (ti == tj) ? vi : *(const float4*)(srcJ + d4 * 4);
            *(float4*)&Wj[r][d4 * 4] = vj;
        }
    }
    __syncthreads();

    const int a = tid >> 4;               // local i
    const int b = tid & 15;               // local j
    const int gi = ti * CTI + a;
    const int gj = tj * CTI + b;

    double val = 0.0;
    if (gj > gi) {
        float dot = 0.0f;
        #pragma unroll 8
        for (int d4 = 0; d4 < DIM / 4; ++d4) {
            float4 ai = *(const float4*)&Wi[a][d4 * 4];
            float4 bj = *(const float4*)&Wj[b][d4 * 4];
            dot = fmaf(ai.x, bj.x, dot);
            dot = fmaf(ai.y, bj.y, dot);
            dot = fmaf(ai.z, bj.z, dot);
            dot = fmaf(ai.w, bj.w, dot);
        }
        const float sqi = g_wsq[c * KCB + gi];
        const float sqj = g_wsq[c * KCB + gj];
        float d2 = __fsub_rn(__fadd_rn(sqi, sqj), __fmul_rn(2.0f, dot));
        val = (double)sqrtf(fmaxf(d2, 0.0f));
    }

    // Block reduce -> single atomic
    #pragma unroll
    for (int off = 16; off; off >>= 1)
        val += __shfl_down_sync(0xffffffffu, val, off);
    const int lane = tid & 31, warp = tid >> 5;
    if (lane == 0) wsum[warp] = val;
    __syncthreads();
    if (tid == 0) {
        double s = 0.0;
        #pragma unroll
        for (int w = 0; w < 8; ++w) s += wsum[w];
        if (s != 0.0) atomicAdd(&g_compact, s);
    }
}

// ---------------- finalize scalars ----------------
__global__ void finalize_kernel(float* __restrict__ out) {
    __shared__ int ssum[256];
    const int t = threadIdx.x;
    int s = 0;
    for (int i = t; i < NC * KCB; i += 256) {
        int d = g_counts[i] - (N_VEC / KCB);
        s += (d < 0) ? -d : d;
    }
    ssum[t] = s;
    __syncthreads();
    for (int off = 128; off; off >>= 1) {
        if (t < off) ssum[t] += ssum[t + off];
        __syncthreads();
    }
    if (t == 0) {
        const size_t base = (size_t)N_VEC * DIM;
        out[base + 0] = (float)(1.25 * g_quant / ((double)N_VEC * (double)DIM));
        out[base + 1] = (float)ssum[0] / 1024.0f;
        out[base + 2] = (float)(2.0 * g_compact / (double)((KCB * (KCB - 1)) / 2));
    }
}

// ---------------- launch ----------------
extern "C" void kernel_launch(void* const* d_in, const int* in_sizes, int n_in,
                              void* d_out, int out_size) {
    const float* x  = (const float*)d_in[0];
    const float* cb = (const float*)d_in[1];
    float* out = (float*)d_out;
    float* out_idx_base = out + (size_t)N_VEC * DIM + 3;

    init_wsq_kernel<<<(NC * KCB + 255) / 256, 256>>>(cb);
    for (int level = 0; level < NC; ++level) {
        vq_level_kernel<<<N_VEC / BM, 256>>>(x, cb, out,
                                             out_idx_base + (size_t)level * N_VEC,
                                             level);
    }
    compact_kernel<<<NC * CPAIRS, 256>>>(cb);
    finalize_kernel<<<1, 256>>>(out);
}

// round 17
// speedup vs baseline: 1.1531x; 1.1531x over previous
#include <cuda_runtime.h>
#include <cstdint>
#include <math_constants.h>

// Problem constants
#define N_VEC 65536
#define DIM   256
#define KCB   1024
#define NC    4

// GEMM tiling
#define BM 128
#define BN 128
#define BK 16
#define PITCH 132   // padded smem pitch (floats)

// Compact-loss tiling
#define CTI 16
#define CNT (KCB / CTI)
#define CPAIRS (CNT * (CNT + 1) / 2)
#define CPITCH 260

// ---------------- device scratch (no allocation allowed) ----------------
__device__ float  g_resid[(size_t)N_VEC * DIM];
__device__ float  g_wsq[NC * KCB];
__device__ int    g_counts[NC * KCB];
__device__ double g_quant;
__device__ double g_compact;

// ---------------- f32x2 packed helpers (Blackwell FFMA2) ----------------
// fma.rn.f32x2 performs TWO independent IEEE fp32 FMAs -> bitwise identical
// to two fmaf() calls. Doubles FMA throughput per issued instruction.
__device__ __forceinline__ unsigned long long pack2(float lo, float hi) {
    unsigned long long r;
    asm("mov.b64 %0, {%1, %2};" : "=l"(r) : "f"(lo), "f"(hi));
    return r;
}
__device__ __forceinline__ void fma2(unsigned long long& d,
                                     unsigned long long a,
                                     unsigned long long b) {
    asm("fma.rn.f32x2 %0, %1, %2, %0;" : "+l"(d) : "l"(a), "l"(b));
}
__device__ __forceinline__ float2 unpack2(unsigned long long v) {
    float2 r;
    asm("mov.b64 {%0, %1}, %2;" : "=f"(r.x), "=f"(r.y) : "l"(v));
    return r;
}

// ---------------- fused init + ||w||^2 ----------------
__global__ void init_wsq_kernel(const float* __restrict__ cb) {
    int i = blockIdx.x * blockDim.x + threadIdx.x;
    if (i >= NC * KCB) return;
    g_counts[i] = 0;
    if (i == 0) { g_quant = 0.0; g_compact = 0.0; }
    const float* w = cb + (size_t)i * DIM;
    float acc = 0.0f;
    for (int d = 0; d < DIM; ++d)
        acc = __fadd_rn(acc, __fmul_rn(w[d], w[d]));
    g_wsq[i] = acc;
}

// ---------------- fused per-level VQ: GEMM + argmin + update ----------------
__global__ __launch_bounds__(256, 2) void vq_level_kernel(
    const float* __restrict__ x,
    const float* __restrict__ cb,
    float* __restrict__ out_q,
    float* __restrict__ out_idx,
    int level)
{
    const float* W   = cb + (size_t)level * KCB * DIM;
    const float* wsq = g_wsq + level * KCB;
    int*  counts     = g_counts + level * KCB;
    const float* resid_src = (level == 0) ? x : g_resid;
    float* resid_dst = g_resid;

    __shared__ float pool[2 * 2 * BK * PITCH];
    __shared__ float rowHalf[2 * BM];
    __shared__ float rowA[BM];
    __shared__ int   bidx[BM];

    float (*As)[BK][PITCH] = reinterpret_cast<float (*)[BK][PITCH]>(pool);
    float (*Bs)[BK][PITCH] = reinterpret_cast<float (*)[BK][PITCH]>(pool + 2 * BK * PITCH);
    float (*redv)[17]      = reinterpret_cast<float (*)[17]>(pool);
    int   (*redi)[17]      = reinterpret_cast<int (*)[17]>(pool + 2176);

    const int tid = threadIdx.x;
    const int tx = tid & 15;        // col group
    const int ty = tid >> 4;        // row group
    const int row0 = blockIdx.x * BM;

    const int rr0 = tid >> 2,         dd0 = (tid & 3) * 4;
    const int rr1 = (tid + 256) >> 2, dd1 = ((tid + 256) & 3) * 4;

    // Per-row A = sum fl(r*r): 2 threads/row (uniform-shift safe for argmin)
    {
        const int r  = tid >> 1;
        const int h  = tid & 1;
        const float* p = resid_src + (size_t)(row0 + r) * DIM + h * (DIM / 2);
        float a = 0.0f;
        for (int d = 0; d < DIM / 2; ++d)
            a = __fadd_rn(a, __fmul_rn(p[d], p[d]));
        rowHalf[r * 2 + h] = a;
    }

    float aA[8];
    float minv[8];
    int   mini[8];

    float4 pa0 = *(const float4*)(resid_src + (size_t)(row0 + rr0) * DIM + dd0);
    float4 pa1 = *(const float4*)(resid_src + (size_t)(row0 + rr1) * DIM + dd1);
    float4 pb0 = *(const float4*)(W + (size_t)rr0 * DIM + dd0);
    float4 pb1 = *(const float4*)(W + (size_t)rr1 * DIM + dd1);
    __syncthreads();

    if (tid < BM)
        rowA[tid] = __fadd_rn(rowHalf[tid * 2], rowHalf[tid * 2 + 1]);
    __syncthreads();

    #pragma unroll
    for (int i = 0; i < 8; ++i) {
        aA[i]   = rowA[ty * 8 + i];
        minv[i] = CUDART_INF_F;
        mini[i] = 0;
    }

    int slice = 0;
    for (int chunk = 0; chunk < KCB / BN; ++chunk) {
        // Paired accumulators: acc2[ip][j] holds rows (ty*8+2ip, ty*8+2ip+1)
        // for column j of this thread. 0ull == (+0.0f, +0.0f).
        unsigned long long acc2[4][8];
        #pragma unroll
        for (int ip = 0; ip < 4; ++ip)
            #pragma unroll
            for (int j = 0; j < 8; ++j) acc2[ip][j] = 0ull;

        for (int s = 0; s < DIM / BK; ++s, ++slice) {
            const int buf = slice & 1;

            As[buf][dd0 + 0][rr0] = pa0.x; As[buf][dd0 + 1][rr0] = pa0.y;
            As[buf][dd0 + 2][rr0] = pa0.z; As[buf][dd0 + 3][rr0] = pa0.w;
            As[buf][dd1 + 0][rr1] = pa1.x; As[buf][dd1 + 1][rr1] = pa1.y;
            As[buf][dd1 + 2][rr1] = pa1.z; As[buf][dd1 + 3][rr1] = pa1.w;
            Bs[buf][dd0 + 0][rr0] = pb0.x; Bs[buf][dd0 + 1][rr0] = pb0.y;
            Bs[buf][dd0 + 2][rr0] = pb0.z; Bs[buf][dd0 + 3][rr0] = pb0.w;
            Bs[buf][dd1 + 0][rr1] = pb1.x; Bs[buf][dd1 + 1][rr1] = pb1.y;
            Bs[buf][dd1 + 2][rr1] = pb1.z; Bs[buf][dd1 + 3][rr1] = pb1.w;

            const bool last = (chunk == KCB / BN - 1) && (s == DIM / BK - 1);
            if (!last) {
                int nchunk = chunk, ns = s + 1;
                if (ns == DIM / BK) { ns = 0; ++nchunk; }
                const int nd0 = ns * BK;
                pa0 = *(const float4*)(resid_src + (size_t)(row0 + rr0) * DIM + nd0 + dd0);
                pa1 = *(const float4*)(resid_src + (size_t)(row0 + rr1) * DIM + nd0 + dd1);
                pb0 = *(const float4*)(W + (size_t)(nchunk * BN + rr0) * DIM + nd0 + dd0);
                pb1 = *(const float4*)(W + (size_t)(nchunk * BN + rr1) * DIM + nd0 + dd1);
            }
            __syncthreads();

            // 8x8 micro-tile via FFMA2: rows paired, columns at tx*4 and
            // tx*4+64 (2-way instead of 4-way smem bank conflicts).
            #pragma unroll
            for (int kk = 0; kk < BK; ++kk) {
                float4 a0 = *(const float4*)&As[buf][kk][ty * 8];
                float4 a1 = *(const float4*)&As[buf][kk][ty * 8 + 4];
                unsigned long long av2[4];
                av2[0] = pack2(a0.x, a0.y);   // adjacent regs -> near-free
                av2[1] = pack2(a0.z, a0.w);
                av2[2] = pack2(a1.x, a1.y);
                av2[3] = pack2(a1.z, a1.w);

                float4 b0 = *(const float4*)&Bs[buf][kk][tx * 4];
                {
                    unsigned long long bb;
                    bb = pack2(b0.x, b0.x);
                    fma2(acc2[0][0], av2[0], bb); fma2(acc2[1][0], av2[1], bb);
                    fma2(acc2[2][0], av2[2], bb); fma2(acc2[3][0], av2[3], bb);
                    bb = pack2(b0.y, b0.y);
                    fma2(acc2[0][1], av2[0], bb); fma2(acc2[1][1], av2[1], bb);
                    fma2(acc2[2][1], av2[2], bb); fma2(acc2[3][1], av2[3], bb);
                    bb = pack2(b0.z, b0.z);
                    fma2(acc2[0][2], av2[0], bb); fma2(acc2[1][2], av2[1], bb);
                    fma2(acc2[2][2], av2[2], bb); fma2(acc2[3][2], av2[3], bb);
                    bb = pack2(b0.w, b0.w);
                    fma2(acc2[0][3], av2[0], bb); fma2(acc2[1][3], av2[1], bb);
                    fma2(acc2[2][3], av2[2], bb); fma2(acc2[3][3], av2[3], bb);
                }
                float4 b1 = *(const float4*)&Bs[buf][kk][tx * 4 + 64];
                {
                    unsigned long long bb;
                    bb = pack2(b1.x, b1.x);
                    fma2(acc2[0][4], av2[0], bb); fma2(acc2[1][4], av2[1], bb);
                    fma2(acc2[2][4], av2[2], bb); fma2(acc2[3][4], av2[3], bb);
                    bb = pack2(b1.y, b1.y);
                    fma2(acc2[0][5], av2[0], bb); fma2(acc2[1][5], av2[1], bb);
                    fma2(acc2[2][5], av2[2], bb); fma2(acc2[3][5], av2[3], bb);
                    bb = pack2(b1.z, b1.z);
                    fma2(acc2[0][6], av2[0], bb); fma2(acc2[1][6], av2[1], bb);
                    fma2(acc2[2][6], av2[2], bb); fma2(acc2[3][6], av2[3], bb);
                    bb = pack2(b1.w, b1.w);
                    fma2(acc2[0][7], av2[0], bb); fma2(acc2[1][7], av2[1], bb);
                    fma2(acc2[2][7], av2[2], bb); fma2(acc2[3][7], av2[3], bb);
                }
            }
        }

        // dist_k = fl( fl(A + B_k) - fl(2*C_k) )
        // Thread's columns: tx*4 + {0..3}, then 64 + tx*4 + {0..3} — ascending
        // within thread; cross-thread ties via lexicographic reduce below.
        #pragma unroll
        for (int j = 0; j < 8; ++j) {
            const int col = chunk * BN +
                ((j < 4) ? (tx * 4 + j) : (64 + tx * 4 + (j - 4)));
            const float bw = __ldg(&wsq[col]);
            #pragma unroll
            for (int ip = 0; ip < 4; ++ip) {
                float2 cc = unpack2(acc2[ip][j]);
                {
                    float t1 = __fadd_rn(aA[2 * ip], bw);
                    float t2 = __fmul_rn(2.0f, cc.x);
                    float d  = __fsub_rn(t1, t2);
                    if (d < minv[2 * ip]) { minv[2 * ip] = d; mini[2 * ip] = col; }
                }
                {
                    float t1 = __fadd_rn(aA[2 * ip + 1], bw);
                    float t2 = __fmul_rn(2.0f, cc.y);
                    float d  = __fsub_rn(t1, t2);
                    if (d < minv[2 * ip + 1]) { minv[2 * ip + 1] = d; mini[2 * ip + 1] = col; }
                }
            }
        }
    }

    __syncthreads();   // before aliasing pool as reduction scratch

    #pragma unroll
    for (int i = 0; i < 8; ++i) {
        redv[ty * 8 + i][tx] = minv[i];
        redi[ty * 8 + i][tx] = mini[i];
    }
    __syncthreads();
    if (tid < BM) {
        float bv = redv[tid][0]; int bi = redi[tid][0];
        #pragma unroll
        for (int t = 1; t < 16; ++t) {
            float v = redv[tid][t]; int ii = redi[tid][t];
            if (v < bv || (v == bv && ii < bi)) { bv = v; bi = ii; }
        }
        bidx[tid] = bi;
        out_idx[row0 + tid] = (float)bi;
        atomicAdd(&counts[bi], 1);
    }
    __syncthreads();

    const int warp = tid >> 5, lane = tid & 31;
    const bool first_level = (level == 0);
    const bool write_resid = (level != NC - 1);
    double dacc = 0.0;
    for (int rr = warp; rr < BM; rr += 8) {
        const int R = row0 + rr;
        const int idx = bidx[rr];
        const float4* q4  = (const float4*)(W + (size_t)idx * DIM);
        const float4* x4  = (const float4*)(x + (size_t)R * DIM);
        const float4* rs4 = (const float4*)(resid_src + (size_t)R * DIM);
        float4* qz4 = (float4*)(out_q + (size_t)R * DIM);
        float4* rd4 = (float4*)(resid_dst + (size_t)R * DIM);
        #pragma unroll
        for (int t = 0; t < 2; ++t) {
            const int p = lane + t * 32;
            float4 q  = q4[p];
            float4 xx = x4[p];
            float4 rs = rs4[p];
            float4 nq, nr;
            if (first_level) {
                nq = q;
            } else {
                float4 qz = qz4[p];
                nq.x = __fadd_rn(qz.x, q.x); nq.y = __fadd_rn(qz.y, q.y);
                nq.z = __fadd_rn(qz.z, q.z); nq.w = __fadd_rn(qz.w, q.w);
            }
            nr.x = __fsub_rn(xx.x, nq.x); nr.y = __fsub_rn(xx.y, nq.y);
            nr.z = __fsub_rn(xx.z, nq.z); nr.w = __fsub_rn(xx.w, nq.w);
            qz4[p] = nq;
            if (write_resid) rd4[p] = nr;
            float d0 = __fsub_rn(q.x, rs.x);
            float d1 = __fsub_rn(q.y, rs.y);
            float d2 = __fsub_rn(q.z, rs.z);
            float d3 = __fsub_rn(q.w, rs.w);
            dacc += (double)d0 * d0 + (double)d1 * d1
                  + (double)d2 * d2 + (double)d3 * d3;
        }
    }
    #pragma unroll
    for (int off = 16; off; off >>= 1)
        dacc += __shfl_down_sync(0xffffffffu, dacc, off);
    if (lane == 0) atomicAdd(&g_quant, dacc);
}

// ---------------- compact loss: tiled pdist over codewords ----------------
__global__ __launch_bounds__(256) void compact_kernel(const float* __restrict__ cb) {
    const int c = blockIdx.x / CPAIRS;
    int p = blockIdx.x % CPAIRS;
    int ti = 0;
    while (p >= CNT - ti) { p -= CNT - ti; ++ti; }
    const int tj = ti + p;
    const float* Wl = cb + (size_t)c * KCB * DIM;

    __shared__ float Wi[CTI][CPITCH];
    __shared__ float Wj[CTI][CPITCH];
    __shared__ double wsum[8];

    const int tid = threadIdx.x;
    {
        const int r = tid >> 4;
        const int q = tid & 15;
        const float* srcI = Wl + (size_t)(ti * CTI + r) * DIM;
        const float* srcJ = Wl + (size_t)(tj * CTI + r) * DIM;
        #pragma unroll
        for (int u = 0; u < 4; ++u) {
            const int d4 = q * 4 + u;
            float4 vi = *(const float4*)(srcI + d4 * 4);
            *(float4*)&Wi[r][d4 * 4] = vi;
            float4 vj = (ti == tj) ? vi : *(const float4*)(srcJ + d4 * 4);
            *(float4*)&Wj[r][d4 * 4] = vj;
        }
    }
    __syncthreads();

    const int a = tid >> 4;
    const int b = tid & 15;
    const int gi = ti * CTI + a;
    const int gj = tj * CTI + b;

    double val = 0.0;
    if (gj > gi) {
        float dot = 0.0f;
        #pragma unroll 8
        for (int d4 = 0; d4 < DIM / 4; ++d4) {
            float4 ai = *(const float4*)&Wi[a][d4 * 4];
            float4 bj = *(const float4*)&Wj[b][d4 * 4];
            dot = fmaf(ai.x, bj.x, dot);
            dot = fmaf(ai.y, bj.y, dot);
            dot = fmaf(ai.z, bj.z, dot);
            dot = fmaf(ai.w, bj.w, dot);
        }
        const float sqi = g_wsq[c * KCB + gi];
        const float sqj = g_wsq[c * KCB + gj];
        float d2 = __fsub_rn(__fadd_rn(sqi, sqj), __fmul_rn(2.0f, dot));
        val = (double)sqrtf(fmaxf(d2, 0.0f));
    }

    #pragma unroll
    for (int off = 16; off; off >>= 1)
        val += __shfl_down_sync(0xffffffffu, val, off);
    const int lane = tid & 31, warp = tid >> 5;
    if (lane == 0) wsum[warp] = val;
    __syncthreads();
    if (tid == 0) {
        double s = 0.0;
        #pragma unroll
        for (int w = 0; w < 8; ++w) s += wsum[w];
        if (s != 0.0) atomicAdd(&g_compact, s);
    }
}

// ---------------- finalize scalars ----------------
__global__ void finalize_kernel(float* __restrict__ out) {
    __shared__ int ssum[256];
    const int t = threadIdx.x;
    int s = 0;
    for (int i = t; i < NC * KCB; i += 256) {
        int d = g_counts[i] - (N_VEC / KCB);
        s += (d < 0) ? -d : d;
    }
    ssum[t] = s;
    __syncthreads();
    for (int off = 128; off; off >>= 1) {
        if (t < off) ssum[t] += ssum[t + off];
        __syncthreads();
    }
    if (t == 0) {
        const size_t base = (size_t)N_VEC * DIM;
        out[base + 0] = (float)(1.25 * g_quant / ((double)N_VEC * (double)DIM));
        out[base + 1] = (float)ssum[0] / 1024.0f;
        out[base + 2] = (float)(2.0 * g_compact / (double)((KCB * (KCB - 1)) / 2));
    }
}

// ---------------- launch ----------------
extern "C" void kernel_launch(void* const* d_in, const int* in_sizes, int n_in,
                              void* d_out, int out_size) {
    const float* x  = (const float*)d_in[0];
    const float* cb = (const float*)d_in[1];
    float* out = (float*)d_out;
    float* out_idx_base = out + (size_t)N_VEC * DIM + 3;

    init_wsq_kernel<<<(NC * KCB + 255) / 256, 256>>>(cb);
    for (int level = 0; level < NC; ++level) {
        vq_level_kernel<<<N_VEC / BM, 256>>>(x, cb, out,
                                             out_idx_base + (size_t)level * N_VEC,
                                             level);
    }
    compact_kernel<<<NC * CPAIRS, 256>>>(cb);
    finalize_kernel<<<1, 256>>>(out);
}